// round 15
// baseline (speedup 1.0000x reference)
#include <cuda_runtime.h>

#define T_STEPS 2048
#define BATCH   256
#define HID     128
#define NTHREADS 512
#define HSW     144      // swizzled h stride per batch (128 + 4 pads)
#define GHS4    1544     // per-batch: 1536 raw ks-partials + 8 xpart (2 parity x 4)

typedef unsigned long long u64;

__device__ __forceinline__ u64 ffma2(u64 a, u64 b, u64 c) {
    u64 d;
    asm("fma.rn.f32x2 %0, %1, %2, %3;" : "=l"(d) : "l"(a), "l"(b), "l"(c));
    return d;
}
__device__ __forceinline__ float hsum2(u64 v) {
    float x, y;
    asm("mov.b64 {%0, %1}, %2;" : "=f"(x), "=f"(y) : "l"(v));
    return x + y;
}

__global__ void __launch_bounds__(NTHREADS, 1)
gru_impute_kernel(const float* __restrict__ x,     // [B, T] (I=1)
                  const float* __restrict__ Wih,   // [384, 1]
                  const float* __restrict__ Whh,   // [384, 128]
                  const float* __restrict__ bih,   // [384]
                  const float* __restrict__ bhh,   // [384]
                  const float* __restrict__ Wfc,   // [1, 128]
                  const float* __restrict__ bfc,   // [1]
                  float* __restrict__ out)
{
    extern __shared__ float sm[];
    float* hsw = sm;                 // 2 * HSW swizzled hidden state (16B aligned)
    float* ghs = sm + 2 * HSW;       // 2 * GHS4: raw partials [0,1536) + xpart [1536,1544)

    const int tid  = threadIdx.x;
    const int lane = tid & 31;
    const int wrp  = tid >> 5;       // 0..15
    const int ks   = lane & 3;       // k-slice 0..3 (32 k's each)
    const int b0   = blockIdx.x * 2;
    const int r0   = wrp * 24 + (lane >> 2);

    // ---- one-time staging: Whh slices into registers (raw; ALL bias in B) ----
    u64 wr0[16], wr1[16], wr2[16];
    {
        const u64* p0 = reinterpret_cast<const u64*>(Whh + (r0     ) * HID + ks * 32);
        const u64* p1 = reinterpret_cast<const u64*>(Whh + (r0 +  8) * HID + ks * 32);
        const u64* p2 = reinterpret_cast<const u64*>(Whh + (r0 + 16) * HID + ks * 32);
        #pragma unroll
        for (int i = 0; i < 16; ++i) { wr0[i] = __ldg(p0 + i); wr1[i] = __ldg(p1 + i); wr2[i] = __ldg(p2 + i); }
    }
    for (int idx = tid; idx < 2 * HSW; idx += NTHREADS) hsw[idx] = 0.0f;
    if (tid < 8) { ghs[1536 + tid] = 0.0f; ghs[GHS4 + 1536 + tid] = 0.0f; }

    // ---- B-phase per-thread constants (threads 0..255 = warps 0-7) ----
    const int ub = tid & 127;
    const int b  = tid >> 7;
    float wih_r = 0.f, wih_z = 0.f, wih_n = 0.f, br = 0.f, bz = 0.f, bnI = 0.f, bhn = 0.f;
    float wfc = 0.f, bf = 0.f, xn = 0.f;
    if (tid < 256) {
        wih_r = Wih[ub];        br  = bih[ub]       + bhh[ub];
        wih_z = Wih[ub + 128];  bz  = bih[ub + 128] + bhh[ub + 128];
        wih_n = Wih[ub + 256];  bnI = bih[ub + 256];
        bhn   = bhh[ub + 256];
        wfc   = Wfc[ub];
        bf    = bfc[0];
        xn    = __ldg(x + (size_t)(b0 + b) * T_STEPS);
    }
    __syncthreads();

    const ulonglong2* hb0 = reinterpret_cast<const ulonglong2*>(hsw + ks * 36);
    const ulonglong2* hb1 = reinterpret_cast<const ulonglong2*>(hsw + HSW + ks * 36);
    float* pa0 = ghs + wrp * 96 + lane;     // raw partial slot: row*4+ks; +32 per row-group
    float* pa1 = pa0 + GHS4;

    float* newin = out;                      // [T, B]
    float* pred  = out + T_STEPS * BATCH;    // [B, T-1]

    float hreg = 0.0f;                       // B threads: own unit's h, register-resident

    for (int t = 0; t < T_STEPS; ++t) {
        // ========== Phase A: matvec, all 16 warps; raw partials, NO shuffles ==========
        {
            u64 a00 = 0ull, a01 = 0ull, a02 = 0ull;
            u64 a10 = 0ull, a11 = 0ull, a12 = 0ull;
            #pragma unroll
            for (int c = 0; c < 8; ++c) {
                ulonglong2 hv = hb0[c];
                a00 = ffma2(wr0[2 * c],     hv.x, a00);
                a01 = ffma2(wr1[2 * c],     hv.x, a01);
                a02 = ffma2(wr2[2 * c],     hv.x, a02);
                a00 = ffma2(wr0[2 * c + 1], hv.y, a00);
                a01 = ffma2(wr1[2 * c + 1], hv.y, a01);
                a02 = ffma2(wr2[2 * c + 1], hv.y, a02);
            }
            #pragma unroll
            for (int c = 0; c < 8; ++c) {
                ulonglong2 hv = hb1[c];
                a10 = ffma2(wr0[2 * c],     hv.x, a10);
                a11 = ffma2(wr1[2 * c],     hv.x, a11);
                a12 = ffma2(wr2[2 * c],     hv.x, a12);
                a10 = ffma2(wr0[2 * c + 1], hv.y, a10);
                a11 = ffma2(wr1[2 * c + 1], hv.y, a11);
                a12 = ffma2(wr2[2 * c + 1], hv.y, a12);
            }
            pa0[0]  = hsum2(a00);            // row r0,    slice ks  (batch 0)
            pa0[32] = hsum2(a01);            // row r0+8
            pa0[64] = hsum2(a02);            // row r0+16
            pa1[0]  = hsum2(a10);            // batch 1
            pa1[32] = hsum2(a11);
            pa1[64] = hsum2(a12);
        }
        __syncthreads();

        // ========== Phase B core: gates + update, threads 0..255 ==========
        if (tid < 256) {
            const float* g4 = ghs + b * GHS4;
            // x_hat partials written at step t-1 into parity buffer (t-1)&1
            const float* xp = g4 + 1536 + (((t & 1) ^ 1) << 2);
            float4 xq = *reinterpret_cast<const float4*>(xp);
            float xh = (xq.x + xq.y) + (xq.z + xq.w) + bf;

            float4 pr = *reinterpret_cast<const float4*>(g4 + 4 * ub);
            float4 pz = *reinterpret_cast<const float4*>(g4 + 512 + 4 * ub);
            float4 pn = *reinterpret_cast<const float4*>(g4 + 1024 + 4 * ub);

            float xt = xn;
            if (t + 1 < T_STEPS)
                xn = __ldg(x + (size_t)(b0 + b) * T_STEPS + t + 1);

            float cur = (t == 0) ? xt : ((xt == 128.0f) ? xh : xt);

            float sr = (pr.x + pr.y) + (pr.z + pr.w);
            float sz = (pz.x + pz.y) + (pz.z + pz.w);
            float sn = (pn.x + pn.y) + (pn.z + pn.w);

            float gr  = fmaf(cur, wih_r, br) + sr;
            float gz  = fmaf(cur, wih_z, bz) + sz;
            float gni = fmaf(cur, wih_n, bnI);

            float r  = __fdividef(1.0f, 1.0f + __expf(-gr));
            float z  = __fdividef(1.0f, 1.0f + __expf(-gz));
            float na = fmaf(r, sn + bhn, gni);
            float e2 = __expf(2.0f * na);
            float n  = 1.0f - __fdividef(2.0f, e2 + 1.0f);   // tanh

            float hnew = fmaf(z, hreg - n, n);               // h from register
            hreg = hnew;
            hsw[b * HSW + ub + (ub >> 5) * 4] = hnew;        // publish for A

            if (ub == 0) {
                newin[t * BATCH + b0 + b] = cur;
                if (t > 0) pred[(size_t)(b0 + b) * (T_STEPS - 1) + (t - 1)] = xh;
            }
        }
        __syncthreads();

        // ========== Deferred x_hat butterfly: off B's critical path, overlaps A(t+1) ==========
        if (tid < 256) {
            float p = hreg * wfc;
            #pragma unroll
            for (int off = 16; off >= 1; off >>= 1)
                p += __shfl_xor_sync(0xffffffffu, p, off);
            if (lane == 0) ghs[b * GHS4 + 1536 + ((t & 1) << 2) + (wrp & 3)] = p;
            // visible to B(t+1) readers via bar1 of step t+1
        }
    }
}

extern "C" void kernel_launch(void* const* d_in, const int* in_sizes, int n_in,
                              void* d_out, int out_size)
{
    (void)in_sizes; (void)n_in; (void)out_size;
    const float* x    = (const float*)d_in[0];
    const float* Wih  = (const float*)d_in[1];
    const float* Whh  = (const float*)d_in[2];
    const float* bih  = (const float*)d_in[3];
    const float* bhh  = (const float*)d_in[4];
    const float* Wfc  = (const float*)d_in[5];
    const float* bfc  = (const float*)d_in[6];
    float* out = (float*)d_out;

    const size_t smem = (size_t)(2 * HSW + 2 * GHS4) * sizeof(float);
    cudaFuncSetAttribute(gru_impute_kernel, cudaFuncAttributeMaxDynamicSharedMemorySize, (int)smem);

    gru_impute_kernel<<<BATCH / 2, NTHREADS, smem>>>(x, Wih, Whh, bih, bhh, Wfc, bfc, out);
}

// round 16
// speedup vs baseline: 1.1123x; 1.1123x over previous
#include <cuda_runtime.h>

#define T_STEPS 2048
#define BATCH   256
#define HID     128
#define NTHREADS 512
#define HSW     144      // swizzled h stride per batch (128 + 4 pads)
#define GHS4    1544     // per-batch: 1536 raw ks-partials + 8 xpart (2 parity x 4)

typedef unsigned long long u64;

__device__ __forceinline__ u64 ffma2(u64 a, u64 b, u64 c) {
    u64 d;
    asm("fma.rn.f32x2 %0, %1, %2, %3;" : "=l"(d) : "l"(a), "l"(b), "l"(c));
    return d;
}
__device__ __forceinline__ float hsum2(u64 v) {
    float x, y;
    asm("mov.b64 {%0, %1}, %2;" : "=f"(x), "=f"(y) : "l"(v));
    return x + y;
}
__device__ __forceinline__ float tanh_fast(float v) {
    float r;
    asm("tanh.approx.f32 %0, %1;" : "=f"(r) : "f"(v));
    return r;
}

__global__ void __launch_bounds__(NTHREADS, 1)
gru_impute_kernel(const float* __restrict__ x,     // [B, T] (I=1)
                  const float* __restrict__ Wih,   // [384, 1]
                  const float* __restrict__ Whh,   // [384, 128]
                  const float* __restrict__ bih,   // [384]
                  const float* __restrict__ bhh,   // [384]
                  const float* __restrict__ Wfc,   // [1, 128]
                  const float* __restrict__ bfc,   // [1]
                  float* __restrict__ out)
{
    extern __shared__ float sm[];
    float* hsw = sm;                 // 2 * HSW swizzled hidden state (16B aligned)
    float* ghs = sm + 2 * HSW;       // 2 * GHS4: raw partials [0,1536) + xpart [1536,1544)

    const int tid  = threadIdx.x;
    const int lane = tid & 31;
    const int wrp  = tid >> 5;       // 0..15
    const int ks   = lane & 3;       // k-slice 0..3 (32 k's each)
    const int b0   = blockIdx.x * 2;
    const int r0   = wrp * 24 + (lane >> 2);

    // ---- one-time staging: Whh slices into registers (raw; ALL bias in B) ----
    u64 wr0[16], wr1[16], wr2[16];
    {
        const u64* p0 = reinterpret_cast<const u64*>(Whh + (r0     ) * HID + ks * 32);
        const u64* p1 = reinterpret_cast<const u64*>(Whh + (r0 +  8) * HID + ks * 32);
        const u64* p2 = reinterpret_cast<const u64*>(Whh + (r0 + 16) * HID + ks * 32);
        #pragma unroll
        for (int i = 0; i < 16; ++i) { wr0[i] = __ldg(p0 + i); wr1[i] = __ldg(p1 + i); wr2[i] = __ldg(p2 + i); }
    }
    for (int idx = tid; idx < 2 * HSW; idx += NTHREADS) hsw[idx] = 0.0f;
    if (tid < 8) { ghs[1536 + tid] = 0.0f; ghs[GHS4 + 1536 + tid] = 0.0f; }

    // ---- B-phase per-thread constants (threads 0..255 = warps 0-7) ----
    const int ub = tid & 127;
    const int b  = tid >> 7;
    float wih_r = 0.f, wih_z = 0.f, wih_n = 0.f, br = 0.f, bz = 0.f, bnI = 0.f, bhn = 0.f;
    float wfc = 0.f, bf = 0.f, xn = 0.f;
    if (tid < 256) {
        wih_r = Wih[ub];        br  = bih[ub]       + bhh[ub];
        wih_z = Wih[ub + 128];  bz  = bih[ub + 128] + bhh[ub + 128];
        wih_n = Wih[ub + 256];  bnI = bih[ub + 256];
        bhn   = bhh[ub + 256];
        wfc   = Wfc[ub];
        bf    = bfc[0];
        xn    = __ldg(x + (size_t)(b0 + b) * T_STEPS);
    }
    __syncthreads();

    const ulonglong2* hb0 = reinterpret_cast<const ulonglong2*>(hsw + ks * 36);
    const ulonglong2* hb1 = reinterpret_cast<const ulonglong2*>(hsw + HSW + ks * 36);
    float* pa0 = ghs + wrp * 96 + lane;     // raw partial slot: row*4+ks; +32 per row-group
    float* pa1 = pa0 + GHS4;

    float* newin = out;                      // [T, B]
    float* pred  = out + T_STEPS * BATCH;    // [B, T-1]

    for (int t = 0; t < T_STEPS; ++t) {
        // ========== Phase A: matvec, all 16 warps; raw partials, NO shuffles ==========
        {
            u64 a00 = 0ull, a01 = 0ull, a02 = 0ull;
            u64 a10 = 0ull, a11 = 0ull, a12 = 0ull;
            #pragma unroll
            for (int c = 0; c < 8; ++c) {
                ulonglong2 hv = hb0[c];
                a00 = ffma2(wr0[2 * c],     hv.x, a00);
                a01 = ffma2(wr1[2 * c],     hv.x, a01);
                a02 = ffma2(wr2[2 * c],     hv.x, a02);
                a00 = ffma2(wr0[2 * c + 1], hv.y, a00);
                a01 = ffma2(wr1[2 * c + 1], hv.y, a01);
                a02 = ffma2(wr2[2 * c + 1], hv.y, a02);
            }
            #pragma unroll
            for (int c = 0; c < 8; ++c) {
                ulonglong2 hv = hb1[c];
                a10 = ffma2(wr0[2 * c],     hv.x, a10);
                a11 = ffma2(wr1[2 * c],     hv.x, a11);
                a12 = ffma2(wr2[2 * c],     hv.x, a12);
                a10 = ffma2(wr0[2 * c + 1], hv.y, a10);
                a11 = ffma2(wr1[2 * c + 1], hv.y, a11);
                a12 = ffma2(wr2[2 * c + 1], hv.y, a12);
            }
            pa0[0]  = hsum2(a00);            // row r0,    slice ks  (batch 0)
            pa0[32] = hsum2(a01);            // row r0+8
            pa0[64] = hsum2(a02);            // row r0+16
            pa1[0]  = hsum2(a10);            // batch 1
            pa1[32] = hsum2(a11);
            pa1[64] = hsum2(a12);
        }
        __syncthreads();

        // ========== Phase B: gates + update, threads 0..255 (float4 gathers) ==========
        if (tid < 256) {
            const float* g4 = ghs + b * GHS4;
            // x_hat partials written at step t-1 into parity buffer (t-1)&1
            const float* xp = g4 + 1536 + (((t & 1) ^ 1) << 2);
            float4 xq = *reinterpret_cast<const float4*>(xp);
            float xh = (xq.x + xq.y) + (xq.z + xq.w) + bf;

            float4 pr = *reinterpret_cast<const float4*>(g4 + 4 * ub);
            float4 pz = *reinterpret_cast<const float4*>(g4 + 512 + 4 * ub);
            float4 pn = *reinterpret_cast<const float4*>(g4 + 1024 + 4 * ub);

            float xt = xn;
            if (t + 1 < T_STEPS)
                xn = __ldg(x + (size_t)(b0 + b) * T_STEPS + t + 1);

            float cur = (t == 0) ? xt : ((xt == 128.0f) ? xh : xt);

            float sr = (pr.x + pr.y) + (pr.z + pr.w);
            float sz = (pz.x + pz.y) + (pz.z + pz.w);
            float sn = (pn.x + pn.y) + (pn.z + pn.w);

            float gr  = fmaf(cur, wih_r, br) + sr;
            float gz  = fmaf(cur, wih_z, bz) + sz;
            float gni = fmaf(cur, wih_n, bnI);

            // sigmoid(x) = 0.5*tanh(0.5x) + 0.5  (MUFU.TANH)
            float r = fmaf(0.5f, tanh_fast(0.5f * gr), 0.5f);
            float z = fmaf(0.5f, tanh_fast(0.5f * gz), 0.5f);
            float na = fmaf(r, sn + bhn, gni);
            float n  = tanh_fast(na);

            const int hidx = b * HSW + ub + (ub >> 5) * 4;   // champion swizzle
            float hold = hsw[hidx];
            float hnew = fmaf(z, hold - n, n);
            hsw[hidx] = hnew;

            if (ub == 0) {
                newin[t * BATCH + b0 + b] = cur;
                if (t > 0) pred[(size_t)(b0 + b) * (T_STEPS - 1) + (t - 1)] = xh;
            }
            // x_hat partial for step t+1 -> parity buffer t&1
            float p = hnew * wfc;
            #pragma unroll
            for (int off = 16; off >= 1; off >>= 1)
                p += __shfl_xor_sync(0xffffffffu, p, off);
            if (lane == 0) ghs[b * GHS4 + 1536 + ((t & 1) << 2) + (wrp & 3)] = p;
        }
        __syncthreads();
    }
}

extern "C" void kernel_launch(void* const* d_in, const int* in_sizes, int n_in,
                              void* d_out, int out_size)
{
    (void)in_sizes; (void)n_in; (void)out_size;
    const float* x    = (const float*)d_in[0];
    const float* Wih  = (const float*)d_in[1];
    const float* Whh  = (const float*)d_in[2];
    const float* bih  = (const float*)d_in[3];
    const float* bhh  = (const float*)d_in[4];
    const float* Wfc  = (const float*)d_in[5];
    const float* bfc  = (const float*)d_in[6];
    float* out = (float*)d_out;

    const size_t smem = (size_t)(2 * HSW + 2 * GHS4) * sizeof(float);
    cudaFuncSetAttribute(gru_impute_kernel, cudaFuncAttributeMaxDynamicSharedMemorySize, (int)smem);

    gru_impute_kernel<<<BATCH / 2, NTHREADS, smem>>>(x, Wih, Whh, bih, bhh, Wfc, bfc, out);
}